// round 13
// baseline (speedup 1.0000x reference)
#include <cuda_runtime.h>
#include <cuda_fp16.h>
#include <cstdint>

// ---------------------------------------------------------------------------
// out[2048,256] = x[2048,32768] @ W[32768,256],
// W[k,r] = U2[i2,r]*U1[i1,r]*U0[i0,r], k = i2*1024 + i1*32 + i0.
//
// fp16 m16n8k16, fp32 accumulate. BN=256 (x touched once), warp tile 32x64.
// Round 13: latency restructure --
//   * 2 K-stages per __syncthreads (4-slot ring, 2-stage buffers)
//   * producer split inside the pair: each LDG->STS distance ~1 stage of MMAs
//   * SPLITS=16 -> 512 CTAs for full-chip packing (vs 256 leaving SMs idle)
// W register-computed from half2 U0 cache; fused split-K reduction.
// ---------------------------------------------------------------------------

#define KT 32768
#define MT 2048
#define NT 256

#define SPLITS 16
#define KCH (KT / SPLITS)        // 2048
#define BK 32
#define NS (KCH / BK)            // 64 stages per CTA
#define NIT (NS / 2)             // 32 stage-pairs
#define BM 64

#define PITCH 80                 // bytes per A row (64 data + 16 pad)
#define SLOT_BYTES (BM * PITCH)  // 5120; buffer = 2 slots; 2 buffers = 20480 B

__device__ float g_part[SPLITS * MT * NT];   // 32 MB split-K partials
__device__ int   g_cnt[MT / BM];             // 32 tile counters (zero-init)

__device__ __forceinline__ uint32_t smem_u32(const void* p) {
    uint32_t a;
    asm("{ .reg .u64 t; cvta.to.shared.u64 t, %1; cvt.u32.u64 %0, t; }" : "=r"(a) : "l"(p));
    return a;
}
__device__ __forceinline__ uint32_t pkh2(float lo, float hi) {
    __half2 h = __floats2half2_rn(lo, hi);
    return *reinterpret_cast<uint32_t*>(&h);
}
__device__ __forceinline__ uint32_t hm2(uint32_t a, uint32_t b) {
    __half2 r = __hmul2(*reinterpret_cast<__half2*>(&a), *reinterpret_cast<__half2*>(&b));
    return *reinterpret_cast<uint32_t*>(&r);
}
__device__ __forceinline__ void ldm4(uint32_t* r, uint32_t addr) {
    asm volatile("ldmatrix.sync.aligned.m8n8.x4.shared.b16 {%0,%1,%2,%3}, [%4];"
                 : "=r"(r[0]), "=r"(r[1]), "=r"(r[2]), "=r"(r[3]) : "r"(addr));
}
__device__ __forceinline__ void mma16816(float* c, const uint32_t* a, uint32_t b0, uint32_t b1) {
    asm volatile(
        "mma.sync.aligned.m16n8k16.row.col.f32.f16.f16.f32 "
        "{%0,%1,%2,%3},{%4,%5,%6,%7},{%8,%9},{%0,%1,%2,%3};"
        : "+f"(c[0]), "+f"(c[1]), "+f"(c[2]), "+f"(c[3])
        : "r"(a[0]), "r"(a[1]), "r"(a[2]), "r"(a[3]), "r"(b0), "r"(b1));
}

// ---------------------------------------------------------------------------
__global__ __launch_bounds__(256, 2) void gemm_kernel(
    const float* __restrict__ x, const float* __restrict__ U0,
    const float* __restrict__ U1, const float* __restrict__ U2,
    float* __restrict__ out) {
    __shared__ __align__(16) char smem[4 * SLOT_BYTES];
    __shared__ int s_flag;
    const uint32_t sb = smem_u32(smem);

    const int tid  = threadIdx.x;
    const int lane = tid & 31;
    const int w    = tid >> 5;
    const int g    = lane >> 2;          // 0..7
    const int tg   = lane & 3;           // 0..3
    const int wm   = (w & 1) * 32;       // 2 warps along M
    const int wn   = (w >> 1) * 64;      // 4 warps along N
    const int m0   = blockIdx.x * BM;
    const int z    = blockIdx.y;
    const long k0  = (long)z * KCH;

    // ---- half2 U0 cache: u0h[nf][ks][h] covers i0 = ks*16 + 2tg + 8h + {0,1}
    uint32_t u0h[8][2][2];
#pragma unroll
    for (int nf = 0; nf < 8; nf++) {
        const int nc = wn + nf * 8 + g;
#pragma unroll
        for (int ks = 0; ks < 2; ks++)
#pragma unroll
            for (int h = 0; h < 2; h++) {
                const int i0 = ks * 16 + 2 * tg + 8 * h;
                u0h[nf][ks][h] = pkh2(U0[i0 * NT + nc], U0[(i0 + 1) * NT + nc]);
            }
    }

    // ---- A producer: thread -> (row = tid>>2, 8 contiguous k at pc*8) ----
    const int prow = tid >> 2;           // 0..63
    const int pc   = tid & 3;            // 0..3
    const float* gx = x + (long)(m0 + prow) * KT + k0 + pc * 8;
    const uint32_t sts0 = (uint32_t)prow * PITCH + (uint32_t)pc * 16;

    // ---- A consumer (ldmatrix): lane -> row/chunk (identical to round 12) --
    const int q = lane >> 3, jj = lane & 7;
    const uint32_t lrow0 = (uint32_t)(wm + (q & 1) * 8 + jj) * PITCH;
    const uint32_t lrow1 = lrow0 + 16 * PITCH;
    const int cq = q >> 1;

    float4 xa, xb;
    // ---- prologue: stages 0,1 -> buffer 0 slots A,B; xr <- stage 2 ----
    xa = *(const float4*)(gx);            xb = *(const float4*)(gx + 4);
    {
        uint4 v; v.x = pkh2(xa.x, xa.y); v.y = pkh2(xa.z, xa.w);
        v.z = pkh2(xb.x, xb.y); v.w = pkh2(xb.z, xb.w);
        *(uint4*)(smem + sts0) = v;
    }
    xa = *(const float4*)(gx + BK);       xb = *(const float4*)(gx + BK + 4);
    {
        uint4 v; v.x = pkh2(xa.x, xa.y); v.y = pkh2(xa.z, xa.w);
        v.z = pkh2(xb.x, xb.y); v.w = pkh2(xb.z, xb.w);
        *(uint4*)(smem + SLOT_BYTES + sts0) = v;
    }
    xa = *(const float4*)(gx + 2 * BK);   xb = *(const float4*)(gx + 2 * BK + 4);

    float acc[2][8][4];
#pragma unroll
    for (int mf = 0; mf < 2; mf++)
#pragma unroll
        for (int nf = 0; nf < 8; nf++)
#pragma unroll
            for (int i = 0; i < 4; i++) acc[mf][nf][i] = 0.0f;

    for (int S = 0; S < NIT; S++) {
        const int s0 = 2 * S;
        const uint32_t rb = sb + (uint32_t)((S & 1) * 2) * SLOT_BYTES;
        char* wbuf = smem + ((S + 1) & 1) * 2 * SLOT_BYTES;

        __syncthreads();   // buffer (S&1) ready; buffer ((S+1)&1) free

        // STS stage s0+2 (in xr) -> write-buffer slot A
        if (s0 + 2 < NS) {
            uint4 v; v.x = pkh2(xa.x, xa.y); v.y = pkh2(xa.z, xa.w);
            v.z = pkh2(xb.x, xb.y); v.w = pkh2(xb.z, xb.w);
            *(uint4*)(wbuf + sts0) = v;
        }
        // LDG stage s0+3 -> xr (covered by stage-s0 MMA batch below)
        if (s0 + 3 < NS) {
            const float* gs = gx + (long)(s0 + 3) * BK;
            xa = *(const float4*)(gs); xb = *(const float4*)(gs + 4);
        }

        // ---- stage s0: p12 + 2x ldmatrix + 32 MMA ----
        {
            const int i1 = s0 & 31;
            const int i2 = z * (KCH / 1024) + (s0 >> 5);
            uint32_t p12h[8];
#pragma unroll
            for (int nf = 0; nf < 8; nf++) {
                const int nc = wn + nf * 8 + g;
                const float p = U2[i2 * NT + nc] * U1[i1 * NT + nc];
                p12h[nf] = pkh2(p, p);
            }
#pragma unroll
            for (int ks = 0; ks < 2; ks++) {
                uint32_t a0[4], a1[4];
                const uint32_t csw = (uint32_t)((ks * 2 + cq) << 4);
                ldm4(a0, rb + lrow0 + csw);
                ldm4(a1, rb + lrow1 + csw);
#pragma unroll
                for (int nf = 0; nf < 8; nf++) {
                    const uint32_t b0 = hm2(p12h[nf], u0h[nf][ks][0]);
                    const uint32_t b1 = hm2(p12h[nf], u0h[nf][ks][1]);
                    mma16816(acc[0][nf], a0, b0, b1);
                    mma16816(acc[1][nf], a1, b0, b1);
                }
            }
        }

        // STS stage s0+3 -> write-buffer slot B (LDG above now landed)
        if (s0 + 3 < NS) {
            uint4 v; v.x = pkh2(xa.x, xa.y); v.y = pkh2(xa.z, xa.w);
            v.z = pkh2(xb.x, xb.y); v.w = pkh2(xb.z, xb.w);
            *(uint4*)(wbuf + SLOT_BYTES + sts0) = v;
        }
        // LDG stage s0+4 -> xr (consumed at top of next iteration)
        if (s0 + 4 < NS) {
            const float* gs = gx + (long)(s0 + 4) * BK;
            xa = *(const float4*)(gs); xb = *(const float4*)(gs + 4);
        }

        // ---- stage s0+1 ----
        {
            const int s1 = s0 + 1;
            const int i1 = s1 & 31;
            const int i2 = z * (KCH / 1024) + (s1 >> 5);
            uint32_t p12h[8];
#pragma unroll
            for (int nf = 0; nf < 8; nf++) {
                const int nc = wn + nf * 8 + g;
                const float p = U2[i2 * NT + nc] * U1[i1 * NT + nc];
                p12h[nf] = pkh2(p, p);
            }
            const uint32_t rb1 = rb + SLOT_BYTES;
#pragma unroll
            for (int ks = 0; ks < 2; ks++) {
                uint32_t a0[4], a1[4];
                const uint32_t csw = (uint32_t)((ks * 2 + cq) << 4);
                ldm4(a0, rb1 + lrow0 + csw);
                ldm4(a1, rb1 + lrow1 + csw);
#pragma unroll
                for (int nf = 0; nf < 8; nf++) {
                    const uint32_t b0 = hm2(p12h[nf], u0h[nf][ks][0]);
                    const uint32_t b1 = hm2(p12h[nf], u0h[nf][ks][1]);
                    mma16816(acc[0][nf], a0, b0, b1);
                    mma16816(acc[1][nf], a1, b0, b1);
                }
            }
        }
    }

    // ---- write split partials ----
    float* part = g_part + (long)z * MT * NT;
#pragma unroll
    for (int mf = 0; mf < 2; mf++) {
        const int mr = m0 + wm + mf * 16 + g;
#pragma unroll
        for (int nf = 0; nf < 8; nf++) {
            const int nc = wn + nf * 8 + tg * 2;
            float2 v0, v1;
            v0.x = acc[mf][nf][0]; v0.y = acc[mf][nf][1];
            v1.x = acc[mf][nf][2]; v1.y = acc[mf][nf][3];
            *(float2*)&part[(long)mr * NT + nc]       = v0;
            *(float2*)&part[(long)(mr + 8) * NT + nc] = v1;
        }
    }

    // ---- fused split-K reduction: last CTA per M-tile sums partials ----
    __threadfence();
    __syncthreads();
    if (tid == 0) {
        const int old = atomicAdd(&g_cnt[blockIdx.x], 1);
        s_flag = (old == SPLITS - 1);
        if (s_flag) g_cnt[blockIdx.x] = 0;       // reset for next replay
    }
    __syncthreads();
    if (s_flag) {
        __threadfence();
#pragma unroll
        for (int it = 0; it < (BM * NT / 4) / 256; it++) {   // 16 float4/thread
            const int f   = tid + 256 * it;
            const int row = f >> 6;               // 64 float4 per 256-col row
            const int c4  = f & 63;
            const long off = (long)(m0 + row) * NT + c4 * 4;
            float4 sum = *(const float4*)(g_part + off);
#pragma unroll
            for (int zz = 1; zz < SPLITS; zz++) {
                const float4 v = *(const float4*)(g_part + (long)zz * MT * NT + off);
                sum.x += v.x; sum.y += v.y; sum.z += v.z; sum.w += v.w;
            }
            *(float4*)(out + off) = sum;
        }
    }
}

// ---------------------------------------------------------------------------
extern "C" void kernel_launch(void* const* d_in, const int* in_sizes, int n_in,
                              void* d_out, int out_size) {
    const float* x  = (const float*)d_in[0];
    const float* U0 = (const float*)d_in[1];
    const float* U1 = (const float*)d_in[2];
    const float* U2 = (const float*)d_in[3];
    float* out = (float*)d_out;

    dim3 grid(MT / BM, SPLITS);   // (32, 16) = 512 CTAs, 2/SM, full-chip pack
    gemm_kernel<<<grid, 256>>>(x, U0, U1, U2, out);
}

// round 15
// speedup vs baseline: 1.1578x; 1.1578x over previous
#include <cuda_runtime.h>
#include <cuda_fp16.h>
#include <cstdint>

// ---------------------------------------------------------------------------
// out[2048,256] = x[2048,32768] @ W[32768,256],
// W[k,r] = U2[i2,r]*U1[i1,r]*U0[i0,r], k = i2*1024 + i1*32 + i0.
//
// fp16 m16n8k16, fp32 accumulate. BN=256 (x touched once), warp tile 32x64,
// 3-slot smem ring (pitch 80, conflict-free ldmatrix), W register-computed.
// Round 14: identical math/structure to round 12; grid changed to a 9-way
// UNEVEN split-K (8x114 + 1x112 BK-stages) -> 288 CTAs = 97% of the 296
// co-residency slots (vs 256 = 86%), still a single wave.
// ---------------------------------------------------------------------------

#define KT 32768
#define MT 2048
#define NT 256

#define SPLITS 9
#define BK 32
#define TOTSTG (KT / BK)         // 1024 stages total
#define BASESTG 114              // z<8: 114 stages; z=8: 112
#define BM 64

#define PITCH 80                 // bytes per A row (64 data + 16 pad)
#define SLOT_BYTES (BM * PITCH)  // 5120

__device__ float g_part[SPLITS * MT * NT];   // 18 MB split-K partials
__device__ int   g_cnt[MT / BM];             // 32 tile counters (zero-init)

__device__ __forceinline__ uint32_t smem_u32(const void* p) {
    uint32_t a;
    asm("{ .reg .u64 t; cvta.to.shared.u64 t, %1; cvt.u32.u64 %0, t; }" : "=r"(a) : "l"(p));
    return a;
}
__device__ __forceinline__ uint32_t pkh2(float lo, float hi) {
    __half2 h = __floats2half2_rn(lo, hi);
    return *reinterpret_cast<uint32_t*>(&h);
}
__device__ __forceinline__ uint32_t hm2(uint32_t a, uint32_t b) {
    __half2 r = __hmul2(*reinterpret_cast<__half2*>(&a), *reinterpret_cast<__half2*>(&b));
    return *reinterpret_cast<uint32_t*>(&r);
}
__device__ __forceinline__ void ldm4(uint32_t* r, uint32_t addr) {
    asm volatile("ldmatrix.sync.aligned.m8n8.x4.shared.b16 {%0,%1,%2,%3}, [%4];"
                 : "=r"(r[0]), "=r"(r[1]), "=r"(r[2]), "=r"(r[3]) : "r"(addr));
}
__device__ __forceinline__ void mma16816(float* c, const uint32_t* a, uint32_t b0, uint32_t b1) {
    asm volatile(
        "mma.sync.aligned.m16n8k16.row.col.f32.f16.f16.f32 "
        "{%0,%1,%2,%3},{%4,%5,%6,%7},{%8,%9},{%0,%1,%2,%3};"
        : "+f"(c[0]), "+f"(c[1]), "+f"(c[2]), "+f"(c[3])
        : "r"(a[0]), "r"(a[1]), "r"(a[2]), "r"(a[3]), "r"(b0), "r"(b1));
}

// ---------------------------------------------------------------------------
__global__ __launch_bounds__(256, 2) void gemm_kernel(
    const float* __restrict__ x, const float* __restrict__ U0,
    const float* __restrict__ U1, const float* __restrict__ U2,
    float* __restrict__ out) {
    __shared__ __align__(16) char smem[3 * SLOT_BYTES];
    __shared__ int s_flag;
    const uint32_t sb = smem_u32(smem);

    const int tid  = threadIdx.x;
    const int lane = tid & 31;
    const int w    = tid >> 5;
    const int g    = lane >> 2;          // 0..7
    const int tg   = lane & 3;           // 0..3
    const int wm   = (w & 1) * 32;       // 2 warps along M (32 rows each)
    const int wn   = (w >> 1) * 64;      // 4 warps along N (64 cols each)
    const int m0   = blockIdx.x * BM;
    const int z    = blockIdx.y;

    // uneven split: stage range [stg0, stg0 + NSz)
    const int stg0 = z * BASESTG;
    const int NSz  = (z < SPLITS - 1) ? BASESTG : (TOTSTG - (SPLITS - 1) * BASESTG);
    const long k0  = (long)stg0 * BK;

    // ---- half2 U0 cache: u0h[nf][ks][h] covers i0 = ks*16 + 2tg + 8h + {0,1}
    uint32_t u0h[8][2][2];
#pragma unroll
    for (int nf = 0; nf < 8; nf++) {
        const int nc = wn + nf * 8 + g;
#pragma unroll
        for (int ks = 0; ks < 2; ks++)
#pragma unroll
            for (int h = 0; h < 2; h++) {
                const int i0 = ks * 16 + 2 * tg + 8 * h;
                u0h[nf][ks][h] = pkh2(U0[i0 * NT + nc], U0[(i0 + 1) * NT + nc]);
            }
    }

    // ---- A producer: thread -> (row = tid>>2, 8 contiguous k at pc*8) ----
    const int prow = tid >> 2;           // 0..63
    const int pc   = tid & 3;            // 0..3
    const float* gx = x + (long)(m0 + prow) * KT + k0 + pc * 8;
    const uint32_t sts0 = (uint32_t)prow * PITCH + (uint32_t)pc * 16;

    // ---- A consumer (ldmatrix): lane -> row/chunk ----
    const int q = lane >> 3, jj = lane & 7;
    const uint32_t lrow0 = (uint32_t)(wm + (q & 1) * 8 + jj) * PITCH;  // m16 tile 0
    const uint32_t lrow1 = lrow0 + 16 * PITCH;                         // m16 tile 1
    const int cq = q >> 1;               // chunk half within k16

    // ---- prologue: stage 0 -> slot 0; xr <- stage 1 ----
    float4 xa = *(const float4*)(gx);
    float4 xb = *(const float4*)(gx + 4);
    {
        uint4 v;
        v.x = pkh2(xa.x, xa.y); v.y = pkh2(xa.z, xa.w);
        v.z = pkh2(xb.x, xb.y); v.w = pkh2(xb.z, xb.w);
        *(uint4*)(smem + sts0) = v;
    }
    xa = *(const float4*)(gx + BK);
    xb = *(const float4*)(gx + BK + 4);

    float acc[2][8][4];
#pragma unroll
    for (int mf = 0; mf < 2; mf++)
#pragma unroll
        for (int nf = 0; nf < 8; nf++)
#pragma unroll
            for (int i = 0; i < 4; i++) acc[mf][nf][i] = 0.0f;

    for (int s = 0; s < NSz; s++) {
        // store stage s+1 (loaded at iter s-1) -> slot (s+1)%3
        if (s + 1 < NSz) {
            uint4 v;
            v.x = pkh2(xa.x, xa.y); v.y = pkh2(xa.z, xa.w);
            v.z = pkh2(xb.x, xb.y); v.w = pkh2(xb.z, xb.w);
            *(uint4*)(smem + ((s + 1) % 3) * SLOT_BYTES + sts0) = v;
        }
        // load stage s+2 into regs (~1 full stage of latency coverage)
        if (s + 2 < NSz) {
            const float* gs = gx + (long)(s + 2) * BK;
            xa = *(const float4*)(gs);
            xb = *(const float4*)(gs + 4);
        }

        // per-stage W scalars (U1/U2 are L1-resident); global stage index
        const int sg = stg0 + s;
        const int i1 = sg & 31;
        const int i2 = sg >> 5;
        uint32_t p12h[8];
#pragma unroll
        for (int nf = 0; nf < 8; nf++) {
            const int nc = wn + nf * 8 + g;
            const float p = U2[i2 * NT + nc] * U1[i1 * NT + nc];
            p12h[nf] = pkh2(p, p);
        }

        __syncthreads();

        const uint32_t slotb = sb + (s % 3) * SLOT_BYTES;
#pragma unroll
        for (int ks = 0; ks < 2; ks++) {
            uint32_t a0[4], a1[4];
            const uint32_t csw = (uint32_t)((ks * 2 + cq) << 4);
            ldm4(a0, slotb + lrow0 + csw);
            ldm4(a1, slotb + lrow1 + csw);
#pragma unroll
            for (int nf = 0; nf < 8; nf++) {
                const uint32_t b0 = hm2(p12h[nf], u0h[nf][ks][0]);
                const uint32_t b1 = hm2(p12h[nf], u0h[nf][ks][1]);
                mma16816(acc[0][nf], a0, b0, b1);
                mma16816(acc[1][nf], a1, b0, b1);
            }
        }
    }

    // ---- write split partials ----
    float* part = g_part + (long)z * MT * NT;
#pragma unroll
    for (int mf = 0; mf < 2; mf++) {
        const int mr = m0 + wm + mf * 16 + g;
#pragma unroll
        for (int nf = 0; nf < 8; nf++) {
            const int nc = wn + nf * 8 + tg * 2;
            float2 v0, v1;
            v0.x = acc[mf][nf][0]; v0.y = acc[mf][nf][1];
            v1.x = acc[mf][nf][2]; v1.y = acc[mf][nf][3];
            *(float2*)&part[(long)mr * NT + nc]       = v0;
            *(float2*)&part[(long)(mr + 8) * NT + nc] = v1;
        }
    }

    // ---- fused split-K reduction: last CTA per M-tile sums partials ----
    __threadfence();
    __syncthreads();
    if (tid == 0) {
        const int old = atomicAdd(&g_cnt[blockIdx.x], 1);
        s_flag = (old == SPLITS - 1);
        if (s_flag) g_cnt[blockIdx.x] = 0;       // reset for next replay
    }
    __syncthreads();
    if (s_flag) {
        __threadfence();
#pragma unroll
        for (int it = 0; it < (BM * NT / 4) / 256; it++) {   // 16 float4/thread
            const int f   = tid + 256 * it;
            const int row = f >> 6;               // 64 float4 per 256-col row
            const int c4  = f & 63;
            const long off = (long)(m0 + row) * NT + c4 * 4;
            float4 sum = *(const float4*)(g_part + off);
#pragma unroll
            for (int zz = 1; zz < SPLITS; zz++) {
                const float4 v = *(const float4*)(g_part + (long)zz * MT * NT + off);
                sum.x += v.x; sum.y += v.y; sum.z += v.z; sum.w += v.w;
            }
            *(float4*)(out + off) = sum;
        }
    }
}

// ---------------------------------------------------------------------------
extern "C" void kernel_launch(void* const* d_in, const int* in_sizes, int n_in,
                              void* d_out, int out_size) {
    const float* x  = (const float*)d_in[0];
    const float* U0 = (const float*)d_in[1];
    const float* U1 = (const float*)d_in[2];
    const float* U2 = (const float*)d_in[3];
    float* out = (float*)d_out;

    dim3 grid(MT / BM, SPLITS);   // (32, 9) = 288 CTAs ~= 296 slots, one wave
    gemm_kernel<<<grid, 256>>>(x, U0, U1, U2, out);
}

// round 16
// speedup vs baseline: 1.2321x; 1.0642x over previous
#include <cuda_runtime.h>
#include <cuda_fp16.h>
#include <cstdint>

// ---------------------------------------------------------------------------
// out[2048,256] = x[2048,32768] @ W[32768,256],
// W[k,r] = U2[i2,r]*U1[i1,r]*U0[i0,r], k = i2*1024 + i1*32 + i0.
//
// Round 16: warp-specialized producer/consumer.
//   640 threads: 16 consumer warps (fp16 m16n8k16, warp tile 16x64) +
//   4 producer warps (A: LDG fp32 -> half2 -> STS, 2-stage reg lookahead;
//   p12 table: U2*U1 packed half2, 256 entries/stage).
//   4-slot smem ring, named-barrier full/back handshake (counts 640).
//   Consumers never touch DRAM in the mainloop.
// BN=256 (x read once), BM=64, SPLITS=4 -> 128 CTAs, 1/SM, single wave.
// Fused split-K reduction via per-M-tile arrival counters.
// ---------------------------------------------------------------------------

#define KT 32768
#define MT 2048
#define NT 256

#define SPLITS 4
#define KCH (KT / SPLITS)        // 8192
#define BK 32
#define NS (KCH / BK)            // 256 stages
#define BM 64

#define PITCH 80                 // bytes per A row (64 data + 16 pad)
#define SLOT_BYTES (BM * PITCH)  // 5120
#define NBUF 4
#define P12_OFF (NBUF * SLOT_BYTES)          // 20480
#define SMEM_BYTES (P12_OFF + NBUF * 1024)   // 24576

#define NCONS 512
#define THREADS 640

__device__ float g_part[SPLITS * MT * NT];   // 8 MB split-K partials
__device__ int   g_cnt[MT / BM];             // 32 tile counters (zero-init)

__device__ __forceinline__ uint32_t smem_u32(const void* p) {
    uint32_t a;
    asm("{ .reg .u64 t; cvta.to.shared.u64 t, %1; cvt.u32.u64 %0, t; }" : "=r"(a) : "l"(p));
    return a;
}
__device__ __forceinline__ uint32_t pkh2(float lo, float hi) {
    __half2 h = __floats2half2_rn(lo, hi);
    return *reinterpret_cast<uint32_t*>(&h);
}
__device__ __forceinline__ uint32_t hm2(uint32_t a, uint32_t b) {
    __half2 r = __hmul2(*reinterpret_cast<__half2*>(&a), *reinterpret_cast<__half2*>(&b));
    return *reinterpret_cast<uint32_t*>(&r);
}
__device__ __forceinline__ void ldm4(uint32_t* r, uint32_t addr) {
    asm volatile("ldmatrix.sync.aligned.m8n8.x4.shared.b16 {%0,%1,%2,%3}, [%4];"
                 : "=r"(r[0]), "=r"(r[1]), "=r"(r[2]), "=r"(r[3]) : "r"(addr));
}
__device__ __forceinline__ void mma16816(float* c, const uint32_t* a, uint32_t b0, uint32_t b1) {
    asm volatile(
        "mma.sync.aligned.m16n8k16.row.col.f32.f16.f16.f32 "
        "{%0,%1,%2,%3},{%4,%5,%6,%7},{%8,%9},{%0,%1,%2,%3};"
        : "+f"(c[0]), "+f"(c[1]), "+f"(c[2]), "+f"(c[3])
        : "r"(a[0]), "r"(a[1]), "r"(a[2]), "r"(a[3]), "r"(b0), "r"(b1));
}
#define BAR_SYNC(id)   asm volatile("bar.sync %0, %1;"   :: "r"(id), "n"(THREADS) : "memory")
#define BAR_ARRIVE(id) asm volatile("bar.arrive %0, %1;" :: "r"(id), "n"(THREADS) : "memory")

// ---------------------------------------------------------------------------
__global__ __launch_bounds__(THREADS, 1) void gemm_kernel(
    const float* __restrict__ x, const float* __restrict__ U0,
    const float* __restrict__ U1, const float* __restrict__ U2,
    float* __restrict__ out) {
    __shared__ __align__(16) char smem[SMEM_BYTES];
    __shared__ int s_flag;
    const uint32_t sb = smem_u32(smem);

    const int tid  = threadIdx.x;
    const int m0   = blockIdx.x * BM;
    const int z    = blockIdx.y;
    const long k0  = (long)z * KCH;

    if (tid < NCONS) {
        // ================= CONSUMER: 16 warps, tile 16x64 each ==============
        const int lane = tid & 31;
        const int w    = tid >> 5;           // 0..15
        const int g    = lane >> 2;          // 0..7
        const int tg   = lane & 3;           // 0..3
        const int wm   = (w & 3) * 16;       // 4 M groups of 16 rows
        const int wn   = (w >> 2) * 64;      // 4 N groups of 64 cols

        // half2 U0 cache: u0h[nf][ks][h] covers i0 = ks*16 + 2tg + 8h + {0,1}
        uint32_t u0h[8][2][2];
#pragma unroll
        for (int nf = 0; nf < 8; nf++) {
            const int nc = wn + nf * 8 + g;
#pragma unroll
            for (int ks = 0; ks < 2; ks++)
#pragma unroll
                for (int h = 0; h < 2; h++) {
                    const int i0 = ks * 16 + 2 * tg + 8 * h;
                    u0h[nf][ks][h] = pkh2(U0[i0 * NT + nc], U0[(i0 + 1) * NT + nc]);
                }
        }

        // ldmatrix addressing (identical pattern to validated round 12)
        const int q = lane >> 3, jj = lane & 7;
        const uint32_t lrow = (uint32_t)(wm + (q & 1) * 8 + jj) * PITCH;
        const int cq = q >> 1;

        // p12 LDS addresses for this thread's 8 n-columns
        uint32_t paddr[8];
#pragma unroll
        for (int nf = 0; nf < 8; nf++)
            paddr[nf] = (uint32_t)(P12_OFF + (wn + nf * 8 + g) * 4);

        float acc[8][4];
#pragma unroll
        for (int nf = 0; nf < 8; nf++)
#pragma unroll
            for (int i = 0; i < 4; i++) acc[nf][i] = 0.0f;

        for (int s = 0; s < NS; s++) {
            const int slot = s & 3;
            BAR_SYNC(1 + slot);                       // slot data + p12 ready

            uint32_t p12h[8];
            const char* pt = smem + slot * 1024;
#pragma unroll
            for (int nf = 0; nf < 8; nf++)
                p12h[nf] = *(const uint32_t*)(pt + paddr[nf]);

            const uint32_t slotb = sb + slot * SLOT_BYTES;
#pragma unroll
            for (int ks = 0; ks < 2; ks++) {
                uint32_t a[4];
                ldm4(a, slotb + lrow + (uint32_t)((ks * 2 + cq) << 4));
#pragma unroll
                for (int nf = 0; nf < 8; nf++) {
                    const uint32_t b0 = hm2(p12h[nf], u0h[nf][ks][0]);
                    const uint32_t b1 = hm2(p12h[nf], u0h[nf][ks][1]);
                    mma16816(acc[nf], a, b0, b1);
                }
            }
            BAR_ARRIVE(5 + slot);                     // slot free
        }

        // write split partials
        float* part = g_part + (long)z * MT * NT;
        const int mr = m0 + wm + g;
#pragma unroll
        for (int nf = 0; nf < 8; nf++) {
            const int nc = wn + nf * 8 + tg * 2;
            float2 v0, v1;
            v0.x = acc[nf][0]; v0.y = acc[nf][1];
            v1.x = acc[nf][2]; v1.y = acc[nf][3];
            *(float2*)&part[(long)mr * NT + nc]       = v0;
            *(float2*)&part[(long)(mr + 8) * NT + nc] = v1;
        }
    } else {
        // ================= PRODUCER: 4 warps ================================
        const int pt = tid - NCONS;          // 0..127
        const int row = pt >> 1;             // 0..63
        const int cp  = (pt & 1) * 2;        // chunk base 0 or 2
        const float* gx = x + (long)(m0 + row) * KT + k0 + cp * 8;
        const uint32_t sts0 = (uint32_t)row * PITCH + (uint32_t)cp * 16;
        const int nc0 = 2 * pt;              // p12 columns nc0, nc0+1

        float4 r0[4], r1[4];                 // 2-stage register lookahead
#pragma unroll
        for (int qq = 0; qq < 4; qq++) r0[qq] = *(const float4*)(gx + qq * 4);
#pragma unroll
        for (int qq = 0; qq < 4; qq++) r1[qq] = *(const float4*)(gx + BK + qq * 4);

        for (int s = 0; s < NS; s++) {
            const int slot = s & 3;
            if (s >= NBUF) BAR_SYNC(5 + slot);        // wait slot free

            // STS A (stage s, staged 2 iters ago)
            {
                const float4* r = (s & 1) ? r1 : r0;
                uint4 v0, v1;
                v0.x = pkh2(r[0].x, r[0].y); v0.y = pkh2(r[0].z, r[0].w);
                v0.z = pkh2(r[1].x, r[1].y); v0.w = pkh2(r[1].z, r[1].w);
                v1.x = pkh2(r[2].x, r[2].y); v1.y = pkh2(r[2].z, r[2].w);
                v1.z = pkh2(r[3].x, r[3].y); v1.w = pkh2(r[3].z, r[3].w);
                char* sd = smem + slot * SLOT_BYTES;
                *(uint4*)(sd + sts0)      = v0;
                *(uint4*)(sd + sts0 + 16) = v1;
            }
            // p12 table (U1/U2 are L1-resident)
            {
                const int sg = z * NS + s;
                const int i1 = sg & 31;
                const int i2 = sg >> 5;
                const float pa = U2[i2 * NT + nc0]     * U1[i1 * NT + nc0];
                const float pb = U2[i2 * NT + nc0 + 1] * U1[i1 * NT + nc0 + 1];
                uint2 v;
                v.x = pkh2(pa, pa);
                v.y = pkh2(pb, pb);
                *(uint2*)(smem + P12_OFF + slot * 1024 + nc0 * 4) = v;
            }
            asm volatile("membar.cta;" ::: "memory");
            BAR_ARRIVE(1 + slot);                     // slot full

            // LDG stage s+2 into the register slot just drained
            if (s + 2 < NS) {
                const float* gs = gx + (long)(s + 2) * BK;
                float4* r = (s & 1) ? r1 : r0;
#pragma unroll
                for (int qq = 0; qq < 4; qq++) r[qq] = *(const float4*)(gs + qq * 4);
            }
        }
    }

    // ---- fused split-K reduction: last CTA per M-tile sums partials ----
    __threadfence();
    __syncthreads();
    if (tid == 0) {
        const int old = atomicAdd(&g_cnt[blockIdx.x], 1);
        s_flag = (old == SPLITS - 1);
        if (s_flag) g_cnt[blockIdx.x] = 0;            // reset for next replay
    }
    __syncthreads();
    if (s_flag && tid < NCONS) {
        __threadfence();
#pragma unroll
        for (int it = 0; it < (BM * NT / 4) / NCONS; it++) {  // 8 float4/thread
            const int f   = tid + NCONS * it;
            const int row = f >> 6;                   // 64 float4 per 256-col row
            const int c4  = f & 63;
            const long off = (long)(m0 + row) * NT + c4 * 4;
            float4 sum = *(const float4*)(g_part + off);
#pragma unroll
            for (int zz = 1; zz < SPLITS; zz++) {
                const float4 v = *(const float4*)(g_part + (long)zz * MT * NT + off);
                sum.x += v.x; sum.y += v.y; sum.z += v.z; sum.w += v.w;
            }
            *(float4*)(out + off) = sum;
        }
    }
}

// ---------------------------------------------------------------------------
extern "C" void kernel_launch(void* const* d_in, const int* in_sizes, int n_in,
                              void* d_out, int out_size) {
    const float* x  = (const float*)d_in[0];
    const float* U0 = (const float*)d_in[1];
    const float* U1 = (const float*)d_in[2];
    const float* U2 = (const float*)d_in[3];
    float* out = (float*)d_out;

    dim3 grid(MT / BM, SPLITS);   // (32, 4) = 128 CTAs, 1/SM, single wave
    gemm_kernel<<<grid, THREADS>>>(x, U0, U1, U2, out);
}

// round 17
// speedup vs baseline: 1.2702x; 1.0309x over previous
#include <cuda_runtime.h>
#include <cuda_fp16.h>
#include <cstdint>

// ---------------------------------------------------------------------------
// out[2048,256] = x[2048,32768] @ W[32768,256],
// W[k,r] = U2[i2,r]*U1[i1,r]*U0[i0,r], k = i2*1024 + i1*32 + i0.
//
// Round 17: fp16 m16n8k16, BN=256, BM=64, 512 threads (16 warps 16x64).
//  * A: cp.async.cg raw fp32 -> 8-slot smem ring, 6 stages ahead,
//    wait_group 5  => no thread ever waits on a fresh DRAM load.
//  * convert: each thread LDS.128s ITS OWN cp'd 16B (no cross-thread hazard),
//    cvt to half2, STS.64 into 2-slot fp16 ring (pitch 80, R12 layout).
//  * one __syncthreads per stage; p12 register-prefetched one stage ahead.
// SPLITS=4 -> 128 CTAs, 1 CTA/SM. Fused split-K reduction.
// ---------------------------------------------------------------------------

#define KT 32768
#define MT 2048
#define NT 256

#define SPLITS 4
#define KCH (KT / SPLITS)        // 8192
#define BK 32
#define NS (KCH / BK)            // 256 stages
#define BM 64

#define NRAW 8
#define RAW_SLOT 8192            // 64 rows x 128 B fp32
#define PITCH 80                 // fp16 row: 64 B data + 16 pad
#define F16_SLOT (BM * PITCH)    // 5120
#define F16_OFF (NRAW * RAW_SLOT)            // 65536
#define SMEM_BYTES (F16_OFF + 2 * F16_SLOT)  // 75776

#define THREADS 512

__device__ float g_part[SPLITS * MT * NT];   // 8 MB split-K partials
__device__ int   g_cnt[MT / BM];             // 32 tile counters (zero-init)

__device__ __forceinline__ uint32_t smem_u32(const void* p) {
    uint32_t a;
    asm("{ .reg .u64 t; cvta.to.shared.u64 t, %1; cvt.u32.u64 %0, t; }" : "=r"(a) : "l"(p));
    return a;
}
__device__ __forceinline__ uint32_t pkh2(float lo, float hi) {
    __half2 h = __floats2half2_rn(lo, hi);
    return *reinterpret_cast<uint32_t*>(&h);
}
__device__ __forceinline__ uint32_t hm2(uint32_t a, uint32_t b) {
    __half2 r = __hmul2(*reinterpret_cast<__half2*>(&a), *reinterpret_cast<__half2*>(&b));
    return *reinterpret_cast<uint32_t*>(&r);
}
__device__ __forceinline__ void cp16(uint32_t dst, const void* src) {
    asm volatile("cp.async.cg.shared.global [%0], [%1], 16;" :: "r"(dst), "l"(src) : "memory");
}
__device__ __forceinline__ void ldm4(uint32_t* r, uint32_t addr) {
    asm volatile("ldmatrix.sync.aligned.m8n8.x4.shared.b16 {%0,%1,%2,%3}, [%4];"
                 : "=r"(r[0]), "=r"(r[1]), "=r"(r[2]), "=r"(r[3]) : "r"(addr));
}
__device__ __forceinline__ void mma16816(float* c, const uint32_t* a, uint32_t b0, uint32_t b1) {
    asm volatile(
        "mma.sync.aligned.m16n8k16.row.col.f32.f16.f16.f32 "
        "{%0,%1,%2,%3},{%4,%5,%6,%7},{%8,%9},{%0,%1,%2,%3};"
        : "+f"(c[0]), "+f"(c[1]), "+f"(c[2]), "+f"(c[3])
        : "r"(a[0]), "r"(a[1]), "r"(a[2]), "r"(a[3]), "r"(b0), "r"(b1));
}

// ---------------------------------------------------------------------------
__global__ __launch_bounds__(THREADS, 1) void gemm_kernel(
    const float* __restrict__ x, const float* __restrict__ U0,
    const float* __restrict__ U1, const float* __restrict__ U2,
    float* __restrict__ out) {
    extern __shared__ __align__(16) char smem[];
    __shared__ int s_flag;
    const uint32_t sb = smem_u32(smem);

    const int tid  = threadIdx.x;
    const int lane = tid & 31;
    const int w    = tid >> 5;           // 0..15
    const int g    = lane >> 2;          // 0..7
    const int tg   = lane & 3;           // 0..3
    const int wm   = (w & 3) * 16;       // 4 M groups of 16 rows
    const int wn   = (w >> 2) * 64;      // 4 N groups of 64 cols
    const int m0   = blockIdx.x * BM;
    const int z    = blockIdx.y;
    const long k0  = (long)z * KCH;

    // ---- half2 U0 cache: u0h[nf][ks][h] covers i0 = ks*16 + 2tg + 8h + {0,1}
    uint32_t u0h[8][2][2];
#pragma unroll
    for (int nf = 0; nf < 8; nf++) {
        const int nc = wn + nf * 8 + g;
#pragma unroll
        for (int ks = 0; ks < 2; ks++)
#pragma unroll
            for (int h = 0; h < 2; h++) {
                const int i0 = ks * 16 + 2 * tg + 8 * h;
                u0h[nf][ks][h] = pkh2(U0[i0 * NT + nc], U0[(i0 + 1) * NT + nc]);
            }
    }

    // ---- producer/convert mapping: thread -> (row tid>>3, 16B chunk tid&7) --
    const int crow = tid >> 3;                       // 0..63
    const int ckc  = tid & 7;                        // 0..7
    const float* gx = x + (long)(m0 + crow) * KT + k0 + ckc * 4;
    const uint32_t raw_off = (uint32_t)crow * 128 + (uint32_t)ckc * 16;
    const uint32_t f16_off = (uint32_t)crow * PITCH + (uint32_t)ckc * 8;

    // ---- ldmatrix consumer addressing (R12/R16 validated) ----
    const int q = lane >> 3, jj = lane & 7;
    const uint32_t lrow = (uint32_t)(wm + (q & 1) * 8 + jj) * PITCH;
    const int cq = q >> 1;

    // ---- prologue: cp stages 0..5; convert stage 0; p12 stage 0 ----
#pragma unroll
    for (int p = 0; p < 6; p++) {
        cp16(sb + p * RAW_SLOT + raw_off, gx + p * BK);
        asm volatile("cp.async.commit_group;" ::: "memory");
    }
    asm volatile("cp.async.wait_group 5;" ::: "memory");   // stage 0 landed
    {
        float4 rv;
        asm volatile("ld.shared.v4.f32 {%0,%1,%2,%3}, [%4];"
                     : "=f"(rv.x), "=f"(rv.y), "=f"(rv.z), "=f"(rv.w)
                     : "r"(sb + raw_off));
        uint2 v;
        v.x = pkh2(rv.x, rv.y);
        v.y = pkh2(rv.z, rv.w);
        asm volatile("st.shared.v2.b32 [%0], {%1,%2};"
                     :: "r"(sb + F16_OFF + f16_off), "r"(v.x), "r"(v.y) : "memory");
    }
    uint32_t p12h[8];
#pragma unroll
    for (int nf = 0; nf < 8; nf++) {
        const int nc = wn + nf * 8 + g;
        const float p = U2[(z * 8) * NT + nc] * U1[nc];
        p12h[nf] = pkh2(p, p);
    }
    __syncthreads();

    float acc[8][4];
#pragma unroll
    for (int nf = 0; nf < 8; nf++)
#pragma unroll
        for (int i = 0; i < 4; i++) acc[nf][i] = 0.0f;

    for (int s = 0; s < NS; s++) {
        // fire cp for stage s+6 (no wait on it for 6 stages)
        if (s + 6 < NS)
            cp16(sb + ((s + 6) & (NRAW - 1)) * RAW_SLOT + raw_off,
                 gx + (long)(s + 6) * BK);
        asm volatile("cp.async.commit_group;" ::: "memory");
        asm volatile("cp.async.wait_group 5;" ::: "memory");   // raw s+1 ready

        // prefetch p12 operands for stage s+1 (L1-resident)
        float u1n[8], u2n[8];
        if (s + 1 < NS) {
            const int i1n = (s + 1) & 31;
            const int i2n = z * 8 + ((s + 1) >> 5);
#pragma unroll
            for (int nf = 0; nf < 8; nf++) {
                const int nc = wn + nf * 8 + g;
                u2n[nf] = U2[i2n * NT + nc];
                u1n[nf] = U1[i1n * NT + nc];
            }
        }

        // convert raw(s+1) -> fp16 slot (s+1)&1  (own 16B: no hazard)
        if (s + 1 < NS) {
            float4 rv;
            asm volatile("ld.shared.v4.f32 {%0,%1,%2,%3}, [%4];"
                         : "=f"(rv.x), "=f"(rv.y), "=f"(rv.z), "=f"(rv.w)
                         : "r"(sb + ((s + 1) & (NRAW - 1)) * RAW_SLOT + raw_off));
            uint2 v;
            v.x = pkh2(rv.x, rv.y);
            v.y = pkh2(rv.z, rv.w);
            asm volatile("st.shared.v2.b32 [%0], {%1,%2};"
                         :: "r"(sb + F16_OFF + ((s + 1) & 1) * F16_SLOT + f16_off),
                            "r"(v.x), "r"(v.y) : "memory");
        }

        // mma phase on fp16 slot s&1
        const uint32_t slotb = sb + F16_OFF + (s & 1) * F16_SLOT;
#pragma unroll
        for (int ks = 0; ks < 2; ks++) {
            uint32_t a[4];
            ldm4(a, slotb + lrow + (uint32_t)((ks * 2 + cq) << 4));
#pragma unroll
            for (int nf = 0; nf < 8; nf++) {
                const uint32_t b0 = hm2(p12h[nf], u0h[nf][ks][0]);
                const uint32_t b1 = hm2(p12h[nf], u0h[nf][ks][1]);
                mma16816(acc[nf], a, b0, b1);
            }
        }

        // fold prefetched p12
        if (s + 1 < NS) {
#pragma unroll
            for (int nf = 0; nf < 8; nf++) {
                const float p = u2n[nf] * u1n[nf];
                p12h[nf] = pkh2(p, p);
            }
        }

        __syncthreads();   // fp16 slot (s+1)&1 complete for next stage
    }

    // ---- write split partials ----
    float* part = g_part + (long)z * MT * NT;
    const int mr = m0 + wm + g;
#pragma unroll
    for (int nf = 0; nf < 8; nf++) {
        const int nc = wn + nf * 8 + tg * 2;
        float2 v0, v1;
        v0.x = acc[nf][0]; v0.y = acc[nf][1];
        v1.x = acc[nf][2]; v1.y = acc[nf][3];
        *(float2*)&part[(long)mr * NT + nc]       = v0;
        *(float2*)&part[(long)(mr + 8) * NT + nc] = v1;
    }

    // ---- fused split-K reduction: last CTA per M-tile sums partials ----
    __threadfence();
    __syncthreads();
    if (tid == 0) {
        const int old = atomicAdd(&g_cnt[blockIdx.x], 1);
        s_flag = (old == SPLITS - 1);
        if (s_flag) g_cnt[blockIdx.x] = 0;            // reset for next replay
    }
    __syncthreads();
    if (s_flag) {
        __threadfence();
#pragma unroll
        for (int it = 0; it < (BM * NT / 4) / THREADS; it++) {  // 8 f4/thread
            const int f   = tid + THREADS * it;
            const int row = f >> 6;                   // 64 float4 per 256-col row
            const int c4  = f & 63;
            const long off = (long)(m0 + row) * NT + c4 * 4;
            float4 sum = *(const float4*)(g_part + off);
#pragma unroll
            for (int zz = 1; zz < SPLITS; zz++) {
                const float4 v = *(const float4*)(g_part + (long)zz * MT * NT + off);
                sum.x += v.x; sum.y += v.y; sum.z += v.z; sum.w += v.w;
            }
            *(float4*)(out + off) = sum;
        }
    }
}

// ---------------------------------------------------------------------------
extern "C" void kernel_launch(void* const* d_in, const int* in_sizes, int n_in,
                              void* d_out, int out_size) {
    const float* x  = (const float*)d_in[0];
    const float* U0 = (const float*)d_in[1];
    const float* U1 = (const float*)d_in[2];
    const float* U2 = (const float*)d_in[3];
    float* out = (float*)d_out;

    static int smem_set = 0;
    if (!smem_set) {
        cudaFuncSetAttribute(gemm_kernel, cudaFuncAttributeMaxDynamicSharedMemorySize,
                             SMEM_BYTES);
        smem_set = 1;
    }

    dim3 grid(MT / BM, SPLITS);   // (32, 4) = 128 CTAs, 1/SM
    gemm_kernel<<<grid, THREADS, SMEM_BYTES>>>(x, U0, U1, U2, out);
}